// round 1
// baseline (speedup 1.0000x reference)
#include <cuda_runtime.h>

// Problem constants (fixed by the dataset)
#define B_ 8
#define S_ 128
#define D_ 480
#define E_ 8
#define C_ 10
#define F_ 994   // W row stride

// Scratch for per-row precomputed contributions.
// Cj[b,s,k]: node1 (W cols 0:480) + edge_i (W cols 960:968), keyed by the j index
// Ci[b,s,k]: node2 (W cols 480:960) + edge_j (W cols 968:976) + bias, keyed by the i index
__device__ float g_Cj[B_ * S_ * C_];
__device__ float g_Ci[B_ * S_ * C_];

// ---------------------------------------------------------------------------
// Kernel 1: one warp per (b,s) row. Dot gcn[b,s,0:480] with W columns 0:480
// and 480:960 for all 10 outputs; fold in the weight_prob diagonal terms.
// ---------------------------------------------------------------------------
__global__ void precompute_rows(const float* __restrict__ gcn,
                                const float* __restrict__ wp,
                                const float* __restrict__ W,
                                const float* __restrict__ bias) {
    int warp = (blockIdx.x * blockDim.x + threadIdx.x) >> 5;
    int lane = threadIdx.x & 31;
    if (warp >= B_ * S_) return;
    int b = warp >> 7;
    int s = warp & (S_ - 1);

    const float* g = gcn + (size_t)(b * S_ + s) * D_;

    float acc1[C_];
    float acc2[C_];
#pragma unroll
    for (int k = 0; k < C_; k++) { acc1[k] = 0.f; acc2[k] = 0.f; }

    for (int d = lane; d < D_; d += 32) {
        float gv = g[d];
#pragma unroll
        for (int k = 0; k < C_; k++) {
            acc1[k] += gv * W[k * F_ + d];
            acc2[k] += gv * W[k * F_ + 480 + d];
        }
    }

    // warp reduction to lane 0
#pragma unroll
    for (int k = 0; k < C_; k++) {
#pragma unroll
        for (int off = 16; off > 0; off >>= 1) {
            acc1[k] += __shfl_down_sync(0xffffffffu, acc1[k], off);
            acc2[k] += __shfl_down_sync(0xffffffffu, acc2[k], off);
        }
    }

    if (lane == 0) {
        // weight_prob diagonal: wp[b, s, s, 0:8]
        const float* ed = wp + (((size_t)(b * S_ + s) * S_) + s) * E_;
        float e[E_];
#pragma unroll
        for (int q = 0; q < E_; q++) e[q] = ed[q];

#pragma unroll
        for (int k = 0; k < C_; k++) {
            float cj = acc1[k];
            float ci = acc2[k] + bias[k];
#pragma unroll
            for (int q = 0; q < E_; q++) {
                cj += e[q] * W[k * F_ + 960 + q];   // edge_i: varies with j
                ci += e[q] * W[k * F_ + 968 + q];   // edge_j: varies with i
            }
            g_Cj[(b * S_ + s) * C_ + k] = cj;
            g_Ci[(b * S_ + s) * C_ + k] = ci;
        }
    }
}

// ---------------------------------------------------------------------------
// Kernel 2: one block per (b,i), one thread per j. 18 FMAs per output element.
// ---------------------------------------------------------------------------
__global__ __launch_bounds__(S_)
void combine_kernel(const float* __restrict__ label,
                    const float* __restrict__ wp,
                    const float* __restrict__ W,
                    float* __restrict__ out) {
    __shared__ float sWwp[E_][C_];   // W cols 976..983
    __shared__ float sWs[C_][C_];    // W cols 984..993
    __shared__ float sCi[C_];

    int bi = blockIdx.x;             // b*S + i
    int b = bi >> 7;
    int i = bi & (S_ - 1);
    int t = threadIdx.x;             // j

    for (int idx = t; idx < E_ * C_ + C_ * C_ + C_; idx += S_) {
        if (idx < E_ * C_) {
            int e = idx / C_, k = idx % C_;
            sWwp[e][k] = W[k * F_ + 976 + e];
        } else if (idx < E_ * C_ + C_ * C_) {
            int r = idx - E_ * C_;
            int c = r / C_, k = r % C_;
            sWs[c][k] = W[k * F_ + 984 + c];
        } else {
            int k = idx - (E_ * C_ + C_ * C_);
            sCi[k] = g_Ci[bi * C_ + k];
        }
    }
    __syncthreads();

    int j = t;
    size_t pix = ((size_t)bi * S_ + j);

    // start from the row contributions
    float res[C_];
    {
        const float2* cj2 = reinterpret_cast<const float2*>(g_Cj + (b * S_ + j) * C_);
#pragma unroll
        for (int h = 0; h < C_ / 2; h++) {
            float2 v = cj2[h];
            res[2 * h]     = v.x + sCi[2 * h];
            res[2 * h + 1] = v.y + sCi[2 * h + 1];
        }
    }

    // weight_prob[b,i,j,0:8] — 32B aligned, two float4 loads
    float w[E_];
    {
        const float4* p = reinterpret_cast<const float4*>(wp + pix * E_);
        float4 a = p[0], c = p[1];
        w[0] = a.x; w[1] = a.y; w[2] = a.z; w[3] = a.w;
        w[4] = c.x; w[5] = c.y; w[6] = c.z; w[7] = c.w;
    }

    // label_sm[b,i,j,0:10] — 8B aligned, five float2 loads
    float l[C_];
    {
        const float2* p = reinterpret_cast<const float2*>(label + pix * C_);
#pragma unroll
        for (int h = 0; h < C_ / 2; h++) {
            float2 v = p[h];
            l[2 * h] = v.x; l[2 * h + 1] = v.y;
        }
    }

    // triangular masks: ch 1..3 kept when j>=i (upper incl diag),
    //                   ch 4..9 kept when i>=j (lower incl diag)
    float mu = (j >= i) ? 1.f : 0.f;
    float ml = (i >= j) ? 1.f : 0.f;
    l[1] *= mu; l[2] *= mu; l[3] *= mu;
#pragma unroll
    for (int c = 4; c < C_; c++) l[c] *= ml;

#pragma unroll
    for (int k = 0; k < C_; k++) {
#pragma unroll
        for (int e = 0; e < E_; e++) res[k] += w[e] * sWwp[e][k];
#pragma unroll
        for (int c = 0; c < C_; c++) res[k] += l[c] * sWs[c][k];
    }

    // out[b,i,j,0:10]
    float2* o2 = reinterpret_cast<float2*>(out + pix * C_);
#pragma unroll
    for (int h = 0; h < C_ / 2; h++) {
        o2[h] = make_float2(res[2 * h], res[2 * h + 1]);
    }
}

extern "C" void kernel_launch(void* const* d_in, const int* in_sizes, int n_in,
                              void* d_out, int out_size) {
    const float* gcn   = (const float*)d_in[0];   // [8,128,480]
    const float* label = (const float*)d_in[1];   // [8,128,128,10]
    const float* wp    = (const float*)d_in[2];   // [8,128,128,8]
    // d_in[3] = tensor_masks (all ones, unused by the reference math)
    const float* W     = (const float*)d_in[4];   // [10,994]
    const float* bias  = (const float*)d_in[5];   // [10]
    float* out = (float*)d_out;                   // [8,128,128,10]

    // Kernel 1: 1024 warps = 128 blocks x 256 threads
    precompute_rows<<<(B_ * S_ * 32 + 255) / 256, 256>>>(gcn, wp, W, bias);

    // Kernel 2: one block per (b,i)
    combine_kernel<<<B_ * S_, S_>>>(label, wp, W, out);
}

// round 2
// speedup vs baseline: 1.1023x; 1.1023x over previous
#include <cuda_runtime.h>

// Problem constants (fixed by the dataset)
#define B_ 8
#define S_ 128
#define D_ 480
#define E_ 8
#define C_ 10
#define F_ 994   // W row stride

// Scratch for per-row precomputed contributions.
// Cj[b,s,k]: node1 (W cols 0:480) + edge_i (W cols 960:968), keyed by j
// Ci[b,s,k]: node2 (W cols 480:960) + edge_j (W cols 968:976) + bias, keyed by i
__device__ float g_Cj[B_ * S_ * C_];
__device__ float g_Ci[B_ * S_ * C_];

// ---- packed fp32x2 helpers (sm_103a FFMA2 path, PTX-only) --------------------
__device__ __forceinline__ unsigned long long pack2(float lo, float hi) {
    unsigned long long r;
    asm("mov.b64 %0, {%1, %2};" : "=l"(r) : "f"(lo), "f"(hi));
    return r;
}
__device__ __forceinline__ void unpack2(unsigned long long v, float& lo, float& hi) {
    asm("mov.b64 {%0, %1}, %2;" : "=f"(lo), "=f"(hi) : "l"(v));
}
__device__ __forceinline__ unsigned long long fma2(unsigned long long a,
                                                   unsigned long long b,
                                                   unsigned long long c) {
    unsigned long long d;
    asm("fma.rn.f32x2 %0, %1, %2, %3;" : "=l"(d) : "l"(a), "l"(b), "l"(c));
    return d;
}

// ---------------------------------------------------------------------------
// Kernel 1: 128 blocks x 256 threads. Block stages W cols [0:960) for all 10
// outputs into smem as interleaved float2 {W[k,d], W[k,480+d]}. One warp per
// (b,s) row; inner loop = 10 LDS.64 + 10 FFMA2 per d-step.
// ---------------------------------------------------------------------------
__global__ __launch_bounds__(256)
void precompute_rows(const float* __restrict__ gcn,
                     const float* __restrict__ wp,
                     const float* __restrict__ W,
                     const float* __restrict__ bias) {
    __shared__ float2 sW[C_][D_];   // 10*480*8 = 38.4 KB

    int tid = threadIdx.x;
    for (int idx = tid; idx < C_ * D_; idx += 256) {
        int k = idx / D_, d = idx - k * D_;
        sW[k][d] = make_float2(W[k * F_ + d], W[k * F_ + 480 + d]);
    }
    __syncthreads();

    int warp = tid >> 5, lane = tid & 31;
    int row = blockIdx.x * 8 + warp;       // 1024 rows total
    int b = row >> 7;
    int s = row & (S_ - 1);
    const float* g = gcn + (size_t)row * D_;

    unsigned long long acc[C_];
#pragma unroll
    for (int k = 0; k < C_; k++) acc[k] = 0ull;

#pragma unroll
    for (int step = 0; step < D_ / 32; step++) {
        int d = lane + step * 32;
        float gv = g[d];
        unsigned long long g2 = pack2(gv, gv);
#pragma unroll
        for (int k = 0; k < C_; k++) {
            unsigned long long w2 =
                *reinterpret_cast<const unsigned long long*>(&sW[k][d]);
            acc[k] = fma2(g2, w2, acc[k]);
        }
    }

    // unpack + warp-reduce 20 partials
    float a1[C_], a2[C_];
#pragma unroll
    for (int k = 0; k < C_; k++) unpack2(acc[k], a1[k], a2[k]);
#pragma unroll
    for (int k = 0; k < C_; k++) {
#pragma unroll
        for (int off = 16; off > 0; off >>= 1) {
            a1[k] += __shfl_down_sync(0xffffffffu, a1[k], off);
            a2[k] += __shfl_down_sync(0xffffffffu, a2[k], off);
        }
    }

    if (lane == 0) {
        // weight_prob diagonal: wp[b, s, s, 0:8]
        const float* ed = wp + (((size_t)(b * S_ + s) * S_) + s) * E_;
        float e[E_];
#pragma unroll
        for (int q = 0; q < E_; q++) e[q] = ed[q];

#pragma unroll
        for (int k = 0; k < C_; k++) {
            float cj = a1[k];
            float ci = a2[k] + bias[k];
#pragma unroll
            for (int q = 0; q < E_; q++) {
                cj += e[q] * W[k * F_ + 960 + q];   // edge_i: varies with j
                ci += e[q] * W[k * F_ + 968 + q];   // edge_j: varies with i
            }
            g_Cj[row * C_ + k] = cj;
            g_Ci[row * C_ + k] = ci;
        }
    }
}

// ---------------------------------------------------------------------------
// Kernel 2: 256 blocks x 256 threads. Block handles 4 consecutive i rows of
// one batch; each thread computes the pixel pair (i, j), (i+1, j) packed into
// f32x2 lanes. Weights live duplicated in smem (LDS.64 broadcast), Cj is
// staged transposed (conflict-free), Ci broadcast.
// ---------------------------------------------------------------------------
__global__ __launch_bounds__(256)
void combine_kernel(const float* __restrict__ label,
                    const float* __restrict__ wp,
                    const float* __restrict__ W,
                    float* __restrict__ out) {
    __shared__ float2 dWwp[E_][C_];   // W cols 976..983, duplicated lanes
    __shared__ float2 dWs[C_][C_];    // W cols 984..993, duplicated lanes
    __shared__ float  sCjT[C_][S_];   // Cj transposed: [k][j]
    __shared__ float  sCi[4][C_];

    int blk = blockIdx.x;              // 256 blocks
    int b = blk >> 5;                  // 32 blocks per batch
    int i_base = (blk & 31) * 4;
    int t = threadIdx.x;

    if (t < E_ * C_ + C_ * C_) {
        if (t < E_ * C_) {
            int e = t / C_, k = t - e * C_;
            float v = W[k * F_ + 976 + e];
            dWwp[e][k] = make_float2(v, v);
        } else {
            int r = t - E_ * C_;
            int c = r / C_, k = r - c * C_;
            float v = W[k * F_ + 984 + c];
            dWs[c][k] = make_float2(v, v);
        }
    }
    for (int idx = t; idx < S_ * C_; idx += 256) {
        int j = idx / C_, k = idx - j * C_;
        sCjT[k][j] = g_Cj[(b * S_ + j) * C_ + k];
    }
    if (t < 4 * C_) {
        int r = t / C_, k = t - r * C_;
        sCi[r][k] = g_Ci[(b * S_ + i_base + r) * C_ + k];
    }
    __syncthreads();

    int j  = t & (S_ - 1);
    int gh = t >> 7;                   // 0 or 1
    int i0 = i_base + 2 * gh;
    int i1 = i0 + 1;
    size_t p0 = (size_t)(b * S_ + i0) * S_ + j;
    size_t p1 = p0 + S_;

    // weight_prob[.,.,j,0:8] for both pixels, packed per-channel
    unsigned long long wv[E_];
    {
        const float4* q0 = reinterpret_cast<const float4*>(wp + p0 * E_);
        const float4* q1 = reinterpret_cast<const float4*>(wp + p1 * E_);
        float4 a0 = q0[0], a1 = q0[1];
        float4 c0 = q1[0], c1 = q1[1];
        wv[0] = pack2(a0.x, c0.x); wv[1] = pack2(a0.y, c0.y);
        wv[2] = pack2(a0.z, c0.z); wv[3] = pack2(a0.w, c0.w);
        wv[4] = pack2(a1.x, c1.x); wv[5] = pack2(a1.y, c1.y);
        wv[6] = pack2(a1.z, c1.z); wv[7] = pack2(a1.w, c1.w);
    }

    // label_sm for both pixels, masked, packed per-channel
    float l0[C_], l1[C_];
    {
        const float2* q0 = reinterpret_cast<const float2*>(label + p0 * C_);
        const float2* q1 = reinterpret_cast<const float2*>(label + p1 * C_);
#pragma unroll
        for (int h = 0; h < C_ / 2; h++) {
            float2 v0 = q0[h], v1 = q1[h];
            l0[2 * h] = v0.x; l0[2 * h + 1] = v0.y;
            l1[2 * h] = v1.x; l1[2 * h + 1] = v1.y;
        }
    }
    // ch 1..3 kept when j>=i (upper incl diag); ch 4..9 kept when i>=j
    float mu0 = (j >= i0) ? 1.f : 0.f, ml0 = (i0 >= j) ? 1.f : 0.f;
    float mu1 = (j >= i1) ? 1.f : 0.f, ml1 = (i1 >= j) ? 1.f : 0.f;
    l0[1] *= mu0; l0[2] *= mu0; l0[3] *= mu0;
    l1[1] *= mu1; l1[2] *= mu1; l1[3] *= mu1;
#pragma unroll
    for (int c = 4; c < C_; c++) { l0[c] *= ml0; l1[c] *= ml1; }

    unsigned long long lv[C_];
#pragma unroll
    for (int c = 0; c < C_; c++) lv[c] = pack2(l0[c], l1[c]);

    // init accumulators with row contributions
    unsigned long long R[C_];
#pragma unroll
    for (int k = 0; k < C_; k++) {
        float cj = sCjT[k][j];
        R[k] = pack2(cj + sCi[2 * gh][k], cj + sCi[2 * gh + 1][k]);
    }

    // 18 packed FMAs per output channel
#pragma unroll
    for (int e = 0; e < E_; e++) {
#pragma unroll
        for (int k = 0; k < C_; k++) {
            unsigned long long w2 =
                *reinterpret_cast<const unsigned long long*>(&dWwp[e][k]);
            R[k] = fma2(wv[e], w2, R[k]);
        }
    }
#pragma unroll
    for (int c = 0; c < C_; c++) {
#pragma unroll
        for (int k = 0; k < C_; k++) {
            unsigned long long w2 =
                *reinterpret_cast<const unsigned long long*>(&dWs[c][k]);
            R[k] = fma2(lv[c], w2, R[k]);
        }
    }

    // unpack and store both pixels (float2 stores)
    float r0[C_], r1[C_];
#pragma unroll
    for (int k = 0; k < C_; k++) unpack2(R[k], r0[k], r1[k]);

    float2* o0 = reinterpret_cast<float2*>(out + p0 * C_);
    float2* o1 = reinterpret_cast<float2*>(out + p1 * C_);
#pragma unroll
    for (int h = 0; h < C_ / 2; h++) {
        o0[h] = make_float2(r0[2 * h], r0[2 * h + 1]);
        o1[h] = make_float2(r1[2 * h], r1[2 * h + 1]);
    }
}

extern "C" void kernel_launch(void* const* d_in, const int* in_sizes, int n_in,
                              void* d_out, int out_size) {
    const float* gcn   = (const float*)d_in[0];   // [8,128,480]
    const float* label = (const float*)d_in[1];   // [8,128,128,10]
    const float* wp    = (const float*)d_in[2];   // [8,128,128,8]
    // d_in[3] = tensor_masks (all ones, no effect on the reference math)
    const float* W     = (const float*)d_in[4];   // [10,994]
    const float* bias  = (const float*)d_in[5];   // [10]
    float* out = (float*)d_out;                   // [8,128,128,10]

    precompute_rows<<<B_ * S_ / 8, 256>>>(gcn, wp, W, bias);
    combine_kernel<<<B_ * S_ / 4 * 8 / 8, 256>>>(label, wp, W, out);
}

// round 3
// speedup vs baseline: 1.2196x; 1.1064x over previous
#include <cuda_runtime.h>

// Problem constants (fixed by the dataset)
#define B_ 8
#define S_ 128
#define D_ 480
#define E_ 8
#define C_ 10
#define F_ 994   // W row stride
#define H_ 5     // channel pairs

// Per-row precomputed contributions.
// Cj[b,s,k]: node1 (W cols 0:480) + edge_i (W cols 960:968), keyed by j
// Ci[b,s,k]: node2 (W cols 480:960) + edge_j (W cols 968:976) + bias, keyed by i
__device__ float g_Cj[B_ * S_ * C_];
__device__ float g_Ci[B_ * S_ * C_];

typedef unsigned long long u64;

// ---- packed fp32x2 helpers (sm_103a FFMA2 path, PTX-only) -------------------
__device__ __forceinline__ u64 pack2(float lo, float hi) {
    u64 r;
    asm("mov.b64 %0, {%1, %2};" : "=l"(r) : "f"(lo), "f"(hi));
    return r;
}
__device__ __forceinline__ void unpack2(u64 v, float& lo, float& hi) {
    asm("mov.b64 {%0, %1}, %2;" : "=f"(lo), "=f"(hi) : "l"(v));
}
__device__ __forceinline__ u64 fma2(u64 a, u64 b, u64 c) {
    u64 d;
    asm("fma.rn.f32x2 %0, %1, %2, %3;" : "=l"(d) : "l"(a), "l"(b), "l"(c));
    return d;
}
__device__ __forceinline__ u64 add2(u64 a, u64 b) {
    u64 d;
    asm("add.rn.f32x2 %0, %1, %2;" : "=l"(d) : "l"(a), "l"(b));
    return d;
}

// ---------------------------------------------------------------------------
// Kernel 1: 256 blocks x 256 threads. Block handles 4 rows; each row is split
// across 2 warps (interleaved 32-wide d-chunks). W cols [0:960) staged in smem
// as channel-pair float2 planes sW[h][d] (conflict-free LDS.64).
//   h in [0,5):  {W[2h][d],     W[2h+1][d]}       (node1)
//   h in [5,10): {W[2h'][480+d],W[2h'+1][480+d]}  (node2)
// ---------------------------------------------------------------------------
__global__ __launch_bounds__(256)
void precompute_rows(const float* __restrict__ gcn,
                     const float* __restrict__ wp,
                     const float* __restrict__ W,
                     const float* __restrict__ bias) {
    __shared__ float2 sW[2 * H_][D_];    // 38.4 KB
    __shared__ float  red[8][2 * C_];    // per-warp partials

    int t = threadIdx.x;
    for (int idx = t; idx < 2 * H_ * D_; idx += 256) {
        int h = idx / D_, d = idx - h * D_;
        if (h < H_)
            sW[h][d] = make_float2(W[(2 * h) * F_ + d], W[(2 * h + 1) * F_ + d]);
        else {
            int hh = h - H_;
            sW[h][d] = make_float2(W[(2 * hh) * F_ + 480 + d],
                                   (2 * hh + 1 < C_) ? W[(2 * hh + 1) * F_ + 480 + d] : 0.f);
        }
    }
    __syncthreads();

    int warp = t >> 5, lane = t & 31;
    int r    = warp >> 1;          // 0..3 row within block
    int half = warp & 1;           // d-chunk parity
    int row  = blockIdx.x * 4 + r; // 1024 rows total
    const float* g = gcn + (size_t)row * D_;

    u64 acc1[H_], acc2[H_];
#pragma unroll
    for (int h = 0; h < H_; h++) { acc1[h] = 0ull; acc2[h] = 0ull; }

    for (int c = half; c < D_ / 32; c += 2) {
        int d = c * 32 + lane;
        float gv = g[d];
        u64 g2 = pack2(gv, gv);
#pragma unroll
        for (int h = 0; h < H_; h++) {
            acc1[h] = fma2(g2, *reinterpret_cast<const u64*>(&sW[h][d]), acc1[h]);
            acc2[h] = fma2(g2, *reinterpret_cast<const u64*>(&sW[h + H_][d]), acc2[h]);
        }
    }

    float a1[C_], a2[C_];
#pragma unroll
    for (int h = 0; h < H_; h++) {
        unpack2(acc1[h], a1[2 * h], a1[2 * h + 1]);
        unpack2(acc2[h], a2[2 * h], a2[2 * h + 1]);
    }
#pragma unroll
    for (int k = 0; k < C_; k++) {
#pragma unroll
        for (int off = 16; off > 0; off >>= 1) {
            a1[k] += __shfl_down_sync(0xffffffffu, a1[k], off);
            a2[k] += __shfl_down_sync(0xffffffffu, a2[k], off);
        }
    }
    if (lane == 0) {
#pragma unroll
        for (int k = 0; k < C_; k++) {
            red[warp][k]      = a1[k];
            red[warp][C_ + k] = a2[k];
        }
    }
    __syncthreads();

    // 80 threads finish: combine warp halves, fold edge-diag + bias, store.
    if (t < 4 * 2 * C_) {
        int rr = t / (2 * C_);
        int q  = t - rr * (2 * C_);
        int rw = blockIdx.x * 4 + rr;
        float sum = red[2 * rr][q] + red[2 * rr + 1][q];
        int b = rw >> 7, s = rw & (S_ - 1);
        const float* ed = wp + (((size_t)(b * S_ + s) * S_) + s) * E_;
        if (q < C_) {
            int k = q;
            float cj = sum;
#pragma unroll
            for (int e = 0; e < E_; e++) cj += ed[e] * W[k * F_ + 960 + e];
            g_Cj[rw * C_ + k] = cj;
        } else {
            int k = q - C_;
            float ci = sum + bias[k];
#pragma unroll
            for (int e = 0; e < E_; e++) ci += ed[e] * W[k * F_ + 968 + e];
            g_Ci[rw * C_ + k] = ci;
        }
    }
}

// ---------------------------------------------------------------------------
// Kernel 2: 1024 blocks x 128 threads, one thread per pixel (b,i,j).
// Output channels packed in f32x2 lanes: 90 FFMA2 + 90 broadcast LDS.64.
// Accumulators match output layout -> five STG.64, no unpacking.
// ---------------------------------------------------------------------------
__global__ __launch_bounds__(128)
void combine_kernel(const float* __restrict__ label,
                    const float* __restrict__ wp,
                    const float* __restrict__ W,
                    float* __restrict__ out) {
    __shared__ u64 sWwp[E_][H_];   // {W[2h][976+e], W[2h+1][976+e]}
    __shared__ u64 sWs[C_][H_];    // {W[2h][984+c], W[2h+1][984+c]}

    int t = threadIdx.x;
    if (t < E_ * H_ + C_ * H_) {
        if (t < E_ * H_) {
            int e = t / H_, h = t - e * H_;
            sWwp[e][h] = pack2(W[(2 * h) * F_ + 976 + e], W[(2 * h + 1) * F_ + 976 + e]);
        } else {
            int r = t - E_ * H_;
            int c = r / H_, h = r - c * H_;
            sWs[c][h] = pack2(W[(2 * h) * F_ + 984 + c], W[(2 * h + 1) * F_ + 984 + c]);
        }
    }
    __syncthreads();

    int bi = blockIdx.x;             // b*S + i
    int b = bi >> 7;
    int i = bi & (S_ - 1);
    int j = t;
    size_t pix = (size_t)bi * S_ + j;

    // init accumulators: channel pairs of Cj[b,j] + Ci[b,i] (both 8B-aligned)
    u64 R[H_];
    {
        const u64* cj = reinterpret_cast<const u64*>(g_Cj + (b * S_ + j) * C_);
        const u64* ci = reinterpret_cast<const u64*>(g_Ci + bi * C_);
#pragma unroll
        for (int h = 0; h < H_; h++) R[h] = add2(cj[h], ci[h]);
    }

    // weight_prob[b,i,j,0:8] broadcast packs
    u64 wv[E_];
    {
        const float4* p = reinterpret_cast<const float4*>(wp + pix * E_);
        float4 a = p[0], c = p[1];
        wv[0] = pack2(a.x, a.x); wv[1] = pack2(a.y, a.y);
        wv[2] = pack2(a.z, a.z); wv[3] = pack2(a.w, a.w);
        wv[4] = pack2(c.x, c.x); wv[5] = pack2(c.y, c.y);
        wv[6] = pack2(c.z, c.z); wv[7] = pack2(c.w, c.w);
    }

    // label_sm[b,i,j,0:10], masked, broadcast packs
    u64 lv[C_];
    {
        const float2* p = reinterpret_cast<const float2*>(label + pix * C_);
        float l[C_];
#pragma unroll
        for (int h = 0; h < H_; h++) {
            float2 v = p[h];
            l[2 * h] = v.x; l[2 * h + 1] = v.y;
        }
        // ch 1..3 kept when j>=i (upper incl diag); ch 4..9 kept when i>=j
        float mu = (j >= i) ? 1.f : 0.f;
        float ml = (i >= j) ? 1.f : 0.f;
        l[1] *= mu; l[2] *= mu; l[3] *= mu;
#pragma unroll
        for (int c = 4; c < C_; c++) l[c] *= ml;
#pragma unroll
        for (int c = 0; c < C_; c++) lv[c] = pack2(l[c], l[c]);
    }

    // 18 packed FMAs per channel pair
#pragma unroll
    for (int e = 0; e < E_; e++) {
#pragma unroll
        for (int h = 0; h < H_; h++) R[h] = fma2(wv[e], sWwp[e][h], R[h]);
    }
#pragma unroll
    for (int c = 0; c < C_; c++) {
#pragma unroll
        for (int h = 0; h < H_; h++) R[h] = fma2(lv[c], sWs[c][h], R[h]);
    }

    // store: R[h] == {out[...,2h], out[...,2h+1]}
    u64* o = reinterpret_cast<u64*>(out + pix * C_);
#pragma unroll
    for (int h = 0; h < H_; h++) o[h] = R[h];
}

extern "C" void kernel_launch(void* const* d_in, const int* in_sizes, int n_in,
                              void* d_out, int out_size) {
    const float* gcn   = (const float*)d_in[0];   // [8,128,480]
    const float* label = (const float*)d_in[1];   // [8,128,128,10]
    const float* wp    = (const float*)d_in[2];   // [8,128,128,8]
    // d_in[3] = tensor_masks (all ones, no effect on the reference math)
    const float* W     = (const float*)d_in[4];   // [10,994]
    const float* bias  = (const float*)d_in[5];   // [10]
    float* out = (float*)d_out;                   // [8,128,128,10]

    precompute_rows<<<B_ * S_ / 4, 256>>>(gcn, wp, W, bias);
    combine_kernel<<<B_ * S_, S_>>>(label, wp, W, out);
}

// round 4
// speedup vs baseline: 1.2801x; 1.0496x over previous
#include <cuda_runtime.h>

// Problem constants (fixed by the dataset)
#define B_ 8
#define S_ 128
#define D_ 480
#define E_ 8
#define C_ 10
#define F_ 994    // W row stride

#define PREB 256               // precompute blocks (4 rows each -> 1024 rows)
#define COMBB (B_ * S_)        // combine blocks, one per (b,i)

// Per-row precomputed contributions.
// Cj[b,s,k]: node1 (W cols 0:480) + edge_i (W cols 960:968), keyed by j
// Ci[b,s,k]: node2 (W cols 480:960) + edge_j (W cols 968:976) + bias, keyed by i
__device__ float g_Cj[B_ * S_ * C_];
__device__ float g_Ci[B_ * S_ * C_];
__device__ int g_pre_done;   // zero-initialized; reset by last combine block
__device__ int g_fin;

typedef unsigned long long u64;

// ---- packed fp32x2 helpers (sm_103a FFMA2 path, PTX-only) -------------------
__device__ __forceinline__ u64 pack2(float lo, float hi) {
    u64 r; asm("mov.b64 %0, {%1, %2};" : "=l"(r) : "f"(lo), "f"(hi)); return r;
}
__device__ __forceinline__ void unpack2(u64 v, float& lo, float& hi) {
    asm("mov.b64 {%0, %1}, %2;" : "=f"(lo), "=f"(hi) : "l"(v));
}
__device__ __forceinline__ u64 fma2(u64 a, u64 b, u64 c) {
    u64 d; asm("fma.rn.f32x2 %0, %1, %2, %3;" : "=l"(d) : "l"(a), "l"(b), "l"(c)); return d;
}
__device__ __forceinline__ u64 add2(u64 a, u64 b) {
    u64 d; asm("add.rn.f32x2 %0, %1, %2;" : "=l"(d) : "l"(a), "l"(b)); return d;
}

struct SW {
    u64 wp[E_][5];   // {W[2h][976+e], W[2h+1][976+e]}
    u64 s[C_][5];    // {W[2h][984+c], W[2h+1][984+c]}
};

// Combine math for channel pairs [H0, H0+NH)
template <int H0, int NH>
__device__ __forceinline__ void combine_core(
    const SW& sw, const float* wpv, const float* l,
    const float* __restrict__ cjp, const float* __restrict__ cip,
    float* __restrict__ outp)
{
    u64 R[NH];
#pragma unroll
    for (int h = 0; h < NH; h++) {
        u64 cj = *reinterpret_cast<const u64*>(cjp + 2 * (H0 + h));
        u64 ci = *reinterpret_cast<const u64*>(cip + 2 * (H0 + h));
        R[h] = add2(cj, ci);
    }
#pragma unroll
    for (int e = 0; e < E_; e++) {
        u64 w2 = pack2(wpv[e], wpv[e]);
#pragma unroll
        for (int h = 0; h < NH; h++) R[h] = fma2(w2, sw.wp[e][H0 + h], R[h]);
    }
#pragma unroll
    for (int c = 0; c < C_; c++) {
        u64 l2 = pack2(l[c], l[c]);
#pragma unroll
        for (int h = 0; h < NH; h++) R[h] = fma2(l2, sw.s[c][H0 + h], R[h]);
    }
    u64* o = reinterpret_cast<u64*>(outp + 2 * H0);
#pragma unroll
    for (int h = 0; h < NH; h++) o[h] = R[h];
}

__global__ __launch_bounds__(256)
void fused_kernel(const float* __restrict__ gcn,
                  const float* __restrict__ label,
                  const float* __restrict__ wp,
                  const float* __restrict__ W,
                  const float* __restrict__ bias,
                  float* __restrict__ out)
{
    __shared__ SW sw;
    int t = threadIdx.x;
    int bid = blockIdx.x;

    if (bid < PREB) {
        // ================= PRECOMPUTE (bids 0..255, lowest -> scheduled first)
        int warp = t >> 5, lane = t & 31;
        int row = bid * 4 + (warp >> 1);   // 4 rows/block
        int part = warp & 1;               // 0: Cj (cols 0:480), 1: Ci (cols 480:960)
        const float* g = gcn + (size_t)row * D_;
        const float* Wb = W + part * 480;

        u64 acc[C_];
#pragma unroll
        for (int k = 0; k < C_; k++) acc[k] = 0ull;

#pragma unroll
        for (int it = 0; it < 7; it++) {           // d = 0..447
            int d = it * 64 + lane * 2;
            u64 g2 = *reinterpret_cast<const u64*>(g + d);
#pragma unroll
            for (int k = 0; k < C_; k++)
                acc[k] = fma2(g2, *reinterpret_cast<const u64*>(Wb + k * F_ + d), acc[k]);
        }
        if (lane < 16) {                           // d = 448..479
            int d = 448 + lane * 2;
            u64 g2 = *reinterpret_cast<const u64*>(g + d);
#pragma unroll
            for (int k = 0; k < C_; k++)
                acc[k] = fma2(g2, *reinterpret_cast<const u64*>(Wb + k * F_ + d), acc[k]);
        }

        float s[C_];
#pragma unroll
        for (int k = 0; k < C_; k++) { float lo, hi; unpack2(acc[k], lo, hi); s[k] = lo + hi; }
#pragma unroll
        for (int k = 0; k < C_; k++)
#pragma unroll
            for (int off = 16; off > 0; off >>= 1)
                s[k] += __shfl_down_sync(0xffffffffu, s[k], off);

        if (lane == 0) {
            int b = row >> 7, si = row & (S_ - 1);
            const float* ed = wp + (((size_t)(b * S_ + si) * S_) + si) * E_;
            float e0[E_];
#pragma unroll
            for (int e = 0; e < E_; e++) e0[e] = ed[e];
            if (part == 0) {
#pragma unroll
                for (int k = 0; k < C_; k++) {
                    float v = s[k];
#pragma unroll
                    for (int e = 0; e < E_; e++) v += e0[e] * W[k * F_ + 960 + e];
                    g_Cj[row * C_ + k] = v;
                }
            } else {
#pragma unroll
                for (int k = 0; k < C_; k++) {
                    float v = s[k] + bias[k];
#pragma unroll
                    for (int e = 0; e < E_; e++) v += e0[e] * W[k * F_ + 968 + e];
                    g_Ci[row * C_ + k] = v;
                }
            }
        }
        __syncthreads();
        if (t == 0) { __threadfence(); atomicAdd(&g_pre_done, 1); }
        return;
    }

    // ================= COMBINE (bids 256..1279), one (b,i) per block,
    // 2 threads per pixel: half 0 -> channel pairs {0,1,2}, half 1 -> {3,4}.
    int bi = bid - PREB;
    int b = bi >> 7;
    int i = bi & (S_ - 1);

    // Stage epilogue weights (depends only on W).
    if (t < E_ * 5 + C_ * 5) {
        if (t < E_ * 5) {
            int e = t / 5, h = t - e * 5;
            sw.wp[e][h] = pack2(W[(2 * h) * F_ + 976 + e], W[(2 * h + 1) * F_ + 976 + e]);
        } else {
            int r = t - E_ * 5;
            int c = r / 5, h = r - c * 5;
            sw.s[c][h] = pack2(W[(2 * h) * F_ + 984 + c], W[(2 * h + 1) * F_ + 984 + c]);
        }
    }

    int half = t >> 7;
    int j = t & (S_ - 1);
    size_t pix = (size_t)bi * S_ + j;

    // Issue the big DRAM loads BEFORE waiting on precompute (latency overlap).
    float wpv[E_];
    {
        const float4* p = reinterpret_cast<const float4*>(wp + pix * E_);
        float4 a = p[0], c = p[1];
        wpv[0] = a.x; wpv[1] = a.y; wpv[2] = a.z; wpv[3] = a.w;
        wpv[4] = c.x; wpv[5] = c.y; wpv[6] = c.z; wpv[7] = c.w;
    }
    float l[C_];
    {
        const float2* p = reinterpret_cast<const float2*>(label + pix * C_);
#pragma unroll
        for (int h = 0; h < 5; h++) { float2 v = p[h]; l[2 * h] = v.x; l[2 * h + 1] = v.y; }
    }
    // ch 1..3 kept when j>=i (upper incl diag); ch 4..9 kept when i>=j
    float mu = (j >= i) ? 1.f : 0.f;
    float ml = (i >= j) ? 1.f : 0.f;
    l[1] *= mu; l[2] *= mu; l[3] *= mu;
#pragma unroll
    for (int c = 4; c < C_; c++) l[c] *= ml;

    // Wait for precompute (t0 spins; others park at the barrier).
    if (t == 0) {
        volatile int* pd = &g_pre_done;
        while (*pd < PREB) __nanosleep(64);
        __threadfence();
    }
    __syncthreads();   // also covers the smem weight staging

    const float* cjp = g_Cj + (b * S_ + j) * C_;
    const float* cip = g_Ci + bi * C_;
    float* outp = out + pix * C_;

    if (half == 0) combine_core<0, 3>(sw, wpv, l, cjp, cip, outp);
    else           combine_core<3, 2>(sw, wpv, l, cjp, cip, outp);

    // Last combine block resets the counters for the next graph replay.
    __syncthreads();
    if (t == 0) {
        int f = atomicAdd(&g_fin, 1);
        if (f == COMBB - 1) { g_pre_done = 0; g_fin = 0; }
    }
}

extern "C" void kernel_launch(void* const* d_in, const int* in_sizes, int n_in,
                              void* d_out, int out_size) {
    const float* gcn   = (const float*)d_in[0];   // [8,128,480]
    const float* label = (const float*)d_in[1];   // [8,128,128,10]
    const float* wp    = (const float*)d_in[2];   // [8,128,128,8]
    // d_in[3] = tensor_masks (all ones, no effect on the reference math)
    const float* W     = (const float*)d_in[4];   // [10,994]
    const float* bias  = (const float*)d_in[5];   // [10]
    float* out = (float*)d_out;                   // [8,128,128,10]

    fused_kernel<<<PREB + COMBB, 256>>>(gcn, label, wp, W, bias, out);
}

// round 5
// speedup vs baseline: 1.4074x; 1.0994x over previous
#include <cuda_runtime.h>

// Problem constants (fixed by the dataset)
#define B_ 8
#define S_ 128
#define D_ 480
#define E_ 8
#define C_ 10
#define F_ 994    // W row stride

// Per-row precomputed contributions.
// Cj[b,s,k]: node1 (W cols 0:480) + edge_i (W cols 960:968), keyed by j
// Ci[b,s,k]: node2 (W cols 480:960) + edge_j (W cols 968:976) + bias, keyed by i
__device__ float g_Cj[B_ * S_ * C_];
__device__ float g_Ci[B_ * S_ * C_];

typedef unsigned long long u64;

// ---- packed fp32x2 helpers (sm_103a FFMA2 path, PTX-only) -------------------
__device__ __forceinline__ u64 pack2(float lo, float hi) {
    u64 r; asm("mov.b64 %0, {%1, %2};" : "=l"(r) : "f"(lo), "f"(hi)); return r;
}
__device__ __forceinline__ void unpack2(u64 v, float& lo, float& hi) {
    asm("mov.b64 {%0, %1}, %2;" : "=f"(lo), "=f"(hi) : "l"(v));
}
__device__ __forceinline__ u64 fma2(u64 a, u64 b, u64 c) {
    u64 d; asm("fma.rn.f32x2 %0, %1, %2, %3;" : "=l"(d) : "l"(a), "l"(b), "l"(c)); return d;
}
__device__ __forceinline__ u64 add2(u64 a, u64 b) {
    u64 d; asm("add.rn.f32x2 %0, %1, %2;" : "=l"(d) : "l"(a), "l"(b)); return d;
}

// ---------------------------------------------------------------------------
// Kernel 1: 256 blocks x 256 threads, 4 rows/block, 2 warps/row.
// Direct LDG of W (L1-resident after first touch); f32x2 over d-pairs:
// 150 LDG.64 + 150 FFMA2 per warp.
// ---------------------------------------------------------------------------
__global__ __launch_bounds__(256)
void precompute_rows(const float* __restrict__ gcn,
                     const float* __restrict__ wp,
                     const float* __restrict__ W,
                     const float* __restrict__ bias) {
    int t = threadIdx.x;
    int warp = t >> 5, lane = t & 31;
    int row = blockIdx.x * 4 + (warp >> 1);   // 1024 rows total
    int part = warp & 1;                       // 0: Cj (cols 0:480), 1: Ci (480:960)
    const float* g = gcn + (size_t)row * D_;
    const float* Wb = W + part * 480;

    u64 acc[C_];
#pragma unroll
    for (int k = 0; k < C_; k++) acc[k] = 0ull;

#pragma unroll
    for (int it = 0; it < 7; it++) {           // d = 0..447
        int d = it * 64 + lane * 2;
        u64 g2 = *reinterpret_cast<const u64*>(g + d);
#pragma unroll
        for (int k = 0; k < C_; k++)
            acc[k] = fma2(g2, *reinterpret_cast<const u64*>(Wb + k * F_ + d), acc[k]);
    }
    if (lane < 16) {                           // d = 448..479
        int d = 448 + lane * 2;
        u64 g2 = *reinterpret_cast<const u64*>(g + d);
#pragma unroll
        for (int k = 0; k < C_; k++)
            acc[k] = fma2(g2, *reinterpret_cast<const u64*>(Wb + k * F_ + d), acc[k]);
    }

    float s[C_];
#pragma unroll
    for (int k = 0; k < C_; k++) { float lo, hi; unpack2(acc[k], lo, hi); s[k] = lo + hi; }
#pragma unroll
    for (int k = 0; k < C_; k++)
#pragma unroll
        for (int off = 16; off > 0; off >>= 1)
            s[k] += __shfl_down_sync(0xffffffffu, s[k], off);

    if (lane == 0) {
        int b = row >> 7, si = row & (S_ - 1);
        const float* ed = wp + (((size_t)(b * S_ + si) * S_) + si) * E_;
        float e0[E_];
#pragma unroll
        for (int e = 0; e < E_; e++) e0[e] = ed[e];
        if (part == 0) {
#pragma unroll
            for (int k = 0; k < C_; k++) {
                float v = s[k];
#pragma unroll
                for (int e = 0; e < E_; e++) v += e0[e] * W[k * F_ + 960 + e];
                g_Cj[row * C_ + k] = v;
            }
        } else {
#pragma unroll
            for (int k = 0; k < C_; k++) {
                float v = s[k] + bias[k];
#pragma unroll
                for (int e = 0; e < E_; e++) v += e0[e] * W[k * F_ + 968 + e];
                g_Ci[row * C_ + k] = v;
            }
        }
    }
}

// ---------------------------------------------------------------------------
// Kernel 2: 1024 blocks x 256 threads, one (b,i) row per block.
// ALL global traffic is 128B-dense float4; per-pixel math reads from smem
// with conflict-free padded strides (11 for label, 9 for wp, gcd(.,32)=1).
// 2 threads per pixel: half 0 -> channel pairs {0,1,2}, half 1 -> {3,4}.
// ---------------------------------------------------------------------------
__global__ __launch_bounds__(256)
void combine_kernel(const float* __restrict__ label,
                    const float* __restrict__ wp,
                    const float* __restrict__ W,
                    float* __restrict__ out) {
    __shared__ float sLab[S_ * 11];          // padded stride 11
    __shared__ float sWp[S_ * 9];            // padded stride 9
    __shared__ float sCj[S_ * C_];           // stride 10 (u64-aligned reads)
    __shared__ float sOut[S_ * C_];
    __shared__ u64 sWwp[E_][5];              // {W[2h][976+e], W[2h+1][976+e]}
    __shared__ u64 sWs[C_][5];               // {W[2h][984+c], W[2h+1][984+c]}

    int t = threadIdx.x;
    int bi = blockIdx.x;                     // b*S + i
    int b = bi >> 7;
    int i = bi & (S_ - 1);

    // ---- stage epilogue weights
    if (t < E_ * 5 + C_ * 5) {
        if (t < E_ * 5) {
            int e = t / 5, h = t - e * 5;
            sWwp[e][h] = pack2(W[(2 * h) * F_ + 976 + e], W[(2 * h + 1) * F_ + 976 + e]);
        } else {
            int r = t - E_ * 5;
            int c = r / 5, h = r - c * 5;
            sWs[c][h] = pack2(W[(2 * h) * F_ + 984 + c], W[(2 * h + 1) * F_ + 984 + c]);
        }
    }

    // ---- dense global loads -> smem
    // label row: 1280 floats = 320 float4, scatter to stride-11 layout
    {
        const float4* src = reinterpret_cast<const float4*>(label + (size_t)bi * S_ * C_);
#pragma unroll
        for (int q = t; q < 320; q += 256) {
            float4 v = src[q];
            int p = 4 * q;
            int j0 = p / C_, c0 = p - j0 * C_;
            // 4 consecutive elements; c0 in {0,2,4,6,8} so no row wrap except c0==8
            sLab[j0 * 11 + c0]     = v.x;
            sLab[j0 * 11 + c0 + 1] = v.y;
            if (c0 == 8) {
                sLab[(j0 + 1) * 11]     = v.z;
                sLab[(j0 + 1) * 11 + 1] = v.w;
            } else {
                sLab[j0 * 11 + c0 + 2] = v.z;
                sLab[j0 * 11 + c0 + 3] = v.w;
            }
        }
    }
    // wp row: 1024 floats = 256 float4, scatter to stride-9 layout
    {
        const float4* src = reinterpret_cast<const float4*>(wp + (size_t)bi * S_ * E_);
        float4 v = src[t];
        int p = 4 * t;
        int j0 = p >> 3, e0 = p & 7;         // e0 in {0,4}
        sWp[j0 * 9 + e0]     = v.x;
        sWp[j0 * 9 + e0 + 1] = v.y;
        sWp[j0 * 9 + e0 + 2] = v.z;
        sWp[j0 * 9 + e0 + 3] = v.w;
    }
    // Cj row for batch b: 1280 floats = 320 float4, linear layout
    {
        const float4* src = reinterpret_cast<const float4*>(g_Cj + (size_t)b * S_ * C_);
        float4* dst = reinterpret_cast<float4*>(sCj);
#pragma unroll
        for (int q = t; q < 320; q += 256) dst[q] = src[q];
    }
    __syncthreads();

    // ---- per-pixel math
    int half = t >> 7;                       // 0: pairs {0,1,2}, 1: pairs {3,4}
    int j = t & (S_ - 1);

    // label, masked (scalar smem reads, conflict-free stride 11)
    float l[C_];
#pragma unroll
    for (int c = 0; c < C_; c++) l[c] = sLab[j * 11 + c];
    float mu = (j >= i) ? 1.f : 0.f;         // ch 1..3: upper incl diag
    float ml = (i >= j) ? 1.f : 0.f;         // ch 4..9: lower incl diag
    l[1] *= mu; l[2] *= mu; l[3] *= mu;
#pragma unroll
    for (int c = 4; c < C_; c++) l[c] *= ml;

    float wv[E_];
#pragma unroll
    for (int e = 0; e < E_; e++) wv[e] = sWp[j * 9 + e];

    // Ci[bi] via broadcast global load (same address across block, L1-cached)
    const u64* cip = reinterpret_cast<const u64*>(g_Ci + bi * C_);
    const u64* cjp = reinterpret_cast<const u64*>(sCj + j * C_);

    if (half == 0) {
        u64 R[3];
#pragma unroll
        for (int h = 0; h < 3; h++) R[h] = add2(cjp[h], cip[h]);
#pragma unroll
        for (int e = 0; e < E_; e++) {
            u64 w2 = pack2(wv[e], wv[e]);
#pragma unroll
            for (int h = 0; h < 3; h++) R[h] = fma2(w2, sWwp[e][h], R[h]);
        }
#pragma unroll
        for (int c = 0; c < C_; c++) {
            u64 l2 = pack2(l[c], l[c]);
#pragma unroll
            for (int h = 0; h < 3; h++) R[h] = fma2(l2, sWs[c][h], R[h]);
        }
        u64* o = reinterpret_cast<u64*>(sOut + j * C_);
#pragma unroll
        for (int h = 0; h < 3; h++) o[h] = R[h];
    } else {
        u64 R[2];
#pragma unroll
        for (int h = 0; h < 2; h++) R[h] = add2(cjp[3 + h], cip[3 + h]);
#pragma unroll
        for (int e = 0; e < E_; e++) {
            u64 w2 = pack2(wv[e], wv[e]);
#pragma unroll
            for (int h = 0; h < 2; h++) R[h] = fma2(w2, sWwp[e][3 + h], R[h]);
        }
#pragma unroll
        for (int c = 0; c < C_; c++) {
            u64 l2 = pack2(l[c], l[c]);
#pragma unroll
            for (int h = 0; h < 2; h++) R[h] = fma2(l2, sWs[c][3 + h], R[h]);
        }
        u64* o = reinterpret_cast<u64*>(sOut + j * C_);
#pragma unroll
        for (int h = 0; h < 2; h++) o[3 + h] = R[h];
    }
    __syncthreads();

    // ---- dense store: 320 float4
    {
        const float4* src = reinterpret_cast<const float4*>(sOut);
        float4* dst = reinterpret_cast<float4*>(out + (size_t)bi * S_ * C_);
#pragma unroll
        for (int q = t; q < 320; q += 256) dst[q] = src[q];
    }
}

extern "C" void kernel_launch(void* const* d_in, const int* in_sizes, int n_in,
                              void* d_out, int out_size) {
    const float* gcn   = (const float*)d_in[0];   // [8,128,480]
    const float* label = (const float*)d_in[1];   // [8,128,128,10]
    const float* wp    = (const float*)d_in[2];   // [8,128,128,8]
    // d_in[3] = tensor_masks (all ones, no effect on the reference math)
    const float* W     = (const float*)d_in[4];   // [10,994]
    const float* bias  = (const float*)d_in[5];   // [10]
    float* out = (float*)d_out;                   // [8,128,128,10]

    precompute_rows<<<B_ * S_ / 4, 256>>>(gcn, wp, W, bias);
    combine_kernel<<<B_ * S_, 256>>>(label, wp, W, out);
}

// round 6
// speedup vs baseline: 1.5329x; 1.0892x over previous
#include <cuda_runtime.h>

// Problem constants (fixed by the dataset)
#define B_ 8
#define S_ 128
#define D_ 480
#define E_ 8
#define C_ 10
#define F_ 994    // W row stride

// Per-row precomputed contributions.
// Cj[b,s,k]: node1 (W cols 0:480) + edge_i (W cols 960:968), keyed by j
// Ci[b,s,k]: node2 (W cols 480:960) + edge_j (W cols 968:976) + bias, keyed by i
__device__ float g_Cj[B_ * S_ * C_];
__device__ float g_Ci[B_ * S_ * C_];

typedef unsigned long long u64;

// ---- packed fp32x2 helpers (sm_103a FFMA2 path, PTX-only) -------------------
__device__ __forceinline__ u64 pack2(float lo, float hi) {
    u64 r; asm("mov.b64 %0, {%1, %2};" : "=l"(r) : "f"(lo), "f"(hi)); return r;
}
__device__ __forceinline__ void unpack2(u64 v, float& lo, float& hi) {
    asm("mov.b64 {%0, %1}, %2;" : "=f"(lo), "=f"(hi) : "l"(v));
}
__device__ __forceinline__ u64 fma2(u64 a, u64 b, u64 c) {
    u64 d; asm("fma.rn.f32x2 %0, %1, %2, %3;" : "=l"(d) : "l"(a), "l"(b), "l"(c)); return d;
}
__device__ __forceinline__ u64 add2(u64 a, u64 b) {
    u64 d; asm("add.rn.f32x2 %0, %1, %2;" : "=l"(d) : "l"(a), "l"(b)); return d;
}

// ---------------------------------------------------------------------------
// Kernel 1: 256 blocks x 256 threads, 4 rows/block, one warp per (row, part).
// gcn via float4 (16B-aligned rows); W via LDG.64 (rows only 8B-aligned).
// ---------------------------------------------------------------------------
__global__ __launch_bounds__(256)
void precompute_rows(const float* __restrict__ gcn,
                     const float* __restrict__ wp,
                     const float* __restrict__ W,
                     const float* __restrict__ bias) {
    int t = threadIdx.x;
    int warp = t >> 5, lane = t & 31;
    int row = blockIdx.x * 4 + (warp >> 1);   // 1024 rows total
    int part = warp & 1;                       // 0: Cj (cols 0:480), 1: Ci (480:960)
    const float* g = gcn + (size_t)row * D_;
    const float* Wb = W + part * 480;

    u64 acc[C_];
#pragma unroll
    for (int k = 0; k < C_; k++) acc[k] = 0ull;

#pragma unroll
    for (int it = 0; it < 3; it++) {           // d = 0..383
        int d = it * 128 + lane * 4;
        float4 gv = *reinterpret_cast<const float4*>(g + d);
        u64 gl = pack2(gv.x, gv.y), gh = pack2(gv.z, gv.w);
#pragma unroll
        for (int k = 0; k < C_; k++) {
            const float* wr = Wb + k * F_ + d;
            acc[k] = fma2(gl, *reinterpret_cast<const u64*>(wr), acc[k]);
            acc[k] = fma2(gh, *reinterpret_cast<const u64*>(wr + 2), acc[k]);
        }
    }
    if (lane < 24) {                           // d = 384..479
        int d = 384 + lane * 4;
        float4 gv = *reinterpret_cast<const float4*>(g + d);
        u64 gl = pack2(gv.x, gv.y), gh = pack2(gv.z, gv.w);
#pragma unroll
        for (int k = 0; k < C_; k++) {
            const float* wr = Wb + k * F_ + d;
            acc[k] = fma2(gl, *reinterpret_cast<const u64*>(wr), acc[k]);
            acc[k] = fma2(gh, *reinterpret_cast<const u64*>(wr + 2), acc[k]);
        }
    }

    float s[C_];
#pragma unroll
    for (int k = 0; k < C_; k++) { float lo, hi; unpack2(acc[k], lo, hi); s[k] = lo + hi; }
#pragma unroll
    for (int k = 0; k < C_; k++)
#pragma unroll
        for (int off = 16; off > 0; off >>= 1)
            s[k] += __shfl_down_sync(0xffffffffu, s[k], off);

    if (lane == 0) {
        int b = row >> 7, si = row & (S_ - 1);
        const float* ed = wp + (((size_t)(b * S_ + si) * S_) + si) * E_;
        float e0[E_];
#pragma unroll
        for (int e = 0; e < E_; e++) e0[e] = ed[e];
        if (part == 0) {
#pragma unroll
            for (int k = 0; k < C_; k++) {
                float v = s[k];
#pragma unroll
                for (int e = 0; e < E_; e++) v += e0[e] * W[k * F_ + 960 + e];
                g_Cj[row * C_ + k] = v;
            }
        } else {
#pragma unroll
            for (int k = 0; k < C_; k++) {
                float v = s[k] + bias[k];
#pragma unroll
                for (int e = 0; e < E_; e++) v += e0[e] * W[k * F_ + 968 + e];
                g_Ci[row * C_ + k] = v;
            }
        }
    }
}

// ---------------------------------------------------------------------------
// Kernel 2: 512 blocks x 128 threads. Block = 2 consecutive (b,i) rows (same
// batch), single shared Cj copy. Thread = 2 pixels (j, j+64) x all 5 channel
// pairs: each of the 90 weight LDS.64 is used twice -> per-pixel L1 ops ~2x
// lower. All global I/O dense float4 through smem.
// ---------------------------------------------------------------------------
__global__ __launch_bounds__(128)
void combine_kernel(const float* __restrict__ label,
                    const float* __restrict__ wp,
                    const float* __restrict__ W,
                    float* __restrict__ out) {
    __shared__ __align__(16) float sLab[2][S_ * 11];   // stride 11 (odd)
    __shared__ __align__(16) float sWp[2][S_ * 9];     // stride 9 (odd)
    __shared__ __align__(16) float sCj[S_ * C_];       // linear, stride 10
    __shared__ __align__(16) float sOut[2][S_ * C_];
    __shared__ __align__(16) u64 sWw[18][5];           // {W[2h][col_f], W[2h+1][col_f]}
    __shared__ __align__(16) float sCi[2][C_];

    int t = threadIdx.x;
    int bi0 = blockIdx.x * 2;
    int b = bi0 >> 7;

    // ---- stage epilogue weights: f<8 -> wp col 976+f; f>=8 -> label col 984+(f-8)
    if (t < 90) {
        int f = t / 5, h = t - 5 * f;
        int col = (f < 8) ? (976 + f) : (984 + (f - 8));
        sWw[f][h] = pack2(W[(2 * h) * F_ + col], W[(2 * h + 1) * F_ + col]);
    }
    if (t >= 96 && t < 116) {                 // 20 threads for Ci (2 rows x 10)
        int q = t - 96;
        sCi[q / C_][q % C_] = g_Ci[(bi0 + q / C_) * C_ + q % C_];
    }

    // ---- label: 2 rows = 640 float4, scatter to stride-11 layout
    {
        const float4* src = reinterpret_cast<const float4*>(label + (size_t)bi0 * S_ * C_);
#pragma unroll
        for (int q = t; q < 640; q += 128) {
            float4 v = src[q];
            int p = 4 * q;
            int r0 = p / (S_ * C_);  int m0 = p - r0 * (S_ * C_);
            int j0 = m0 / C_,  c0 = m0 - j0 * C_;          // c0 even, <=8
            int p2 = p + 2;
            int r2 = p2 / (S_ * C_); int m2 = p2 - r2 * (S_ * C_);
            int j2 = m2 / C_,  c2 = m2 - j2 * C_;          // c2 even, <=8
            sLab[r0][j0 * 11 + c0]     = v.x;
            sLab[r0][j0 * 11 + c0 + 1] = v.y;
            sLab[r2][j2 * 11 + c2]     = v.z;
            sLab[r2][j2 * 11 + c2 + 1] = v.w;
        }
    }
    // ---- wp: 2 rows = 512 float4, scatter to stride-9 layout
    {
        const float4* src = reinterpret_cast<const float4*>(wp + (size_t)bi0 * S_ * E_);
#pragma unroll
        for (int q = t; q < 512; q += 128) {
            float4 v = src[q];
            int p = 4 * q;
            int r = p >> 10;  int m = p & 1023;
            int j = m >> 3,   e = m & 7;                   // e in {0,4}
            float* dst = &sWp[r][j * 9 + e];
            dst[0] = v.x; dst[1] = v.y; dst[2] = v.z; dst[3] = v.w;
        }
    }
    // ---- Cj for batch b: 320 float4, linear copy
    {
        const float4* src = reinterpret_cast<const float4*>(g_Cj + (size_t)b * S_ * C_);
        float4* dst = reinterpret_cast<float4*>(sCj);
        for (int q = t; q < 320; q += 128) dst[q] = src[q];
    }
    __syncthreads();

    // ---- compute: 2 pixels per thread
    int r = t >> 6;                           // row in block
    int q = t & 63;
    int i = (bi0 + r) & (S_ - 1);
    int j0 = q, j1 = q + 64;

    float f0[18], f1[18];
#pragma unroll
    for (int e = 0; e < E_; e++) {
        f0[e] = sWp[r][j0 * 9 + e];
        f1[e] = sWp[r][j1 * 9 + e];
    }
#pragma unroll
    for (int c = 0; c < C_; c++) {
        f0[8 + c] = sLab[r][j0 * 11 + c];
        f1[8 + c] = sLab[r][j1 * 11 + c];
    }
    // masks: label ch 1..3 (f=9..11) kept when j>=i; ch 4..9 (f=12..17) when i>=j
    {
        float mu0 = (j0 >= i) ? 1.f : 0.f, ml0 = (i >= j0) ? 1.f : 0.f;
        float mu1 = (j1 >= i) ? 1.f : 0.f, ml1 = (i >= j1) ? 1.f : 0.f;
        f0[9] *= mu0; f0[10] *= mu0; f0[11] *= mu0;
        f1[9] *= mu1; f1[10] *= mu1; f1[11] *= mu1;
#pragma unroll
        for (int f = 12; f < 18; f++) { f0[f] *= ml0; f1[f] *= ml1; }
    }

    u64 A0[5], A1[5];
    {
        const u64* cj0 = reinterpret_cast<const u64*>(sCj + j0 * C_);
        const u64* cj1 = reinterpret_cast<const u64*>(sCj + j1 * C_);
        const u64* ci  = reinterpret_cast<const u64*>(sCi[r]);
#pragma unroll
        for (int h = 0; h < 5; h++) {
            u64 cv = ci[h];
            A0[h] = add2(cj0[h], cv);
            A1[h] = add2(cj1[h], cv);
        }
    }

#pragma unroll
    for (int f = 0; f < 18; f++) {
        u64 p0 = pack2(f0[f], f0[f]);
        u64 p1 = pack2(f1[f], f1[f]);
#pragma unroll
        for (int h = 0; h < 5; h++) {
            u64 w = sWw[f][h];                // one LDS.64, two uses
            A0[h] = fma2(p0, w, A0[h]);
            A1[h] = fma2(p1, w, A1[h]);
        }
    }

    {
        u64* o0 = reinterpret_cast<u64*>(sOut[r] + j0 * C_);
        u64* o1 = reinterpret_cast<u64*>(sOut[r] + j1 * C_);
#pragma unroll
        for (int h = 0; h < 5; h++) { o0[h] = A0[h]; o1[h] = A1[h]; }
    }
    __syncthreads();

    // ---- dense store: 2 rows = 640 float4
    {
        const float4* src = reinterpret_cast<const float4*>(sOut);
        float4* dst = reinterpret_cast<float4*>(out + (size_t)bi0 * S_ * C_);
#pragma unroll
        for (int q2 = t; q2 < 640; q2 += 128) dst[q2] = src[q2];
    }
}

extern "C" void kernel_launch(void* const* d_in, const int* in_sizes, int n_in,
                              void* d_out, int out_size) {
    const float* gcn   = (const float*)d_in[0];   // [8,128,480]
    const float* label = (const float*)d_in[1];   // [8,128,128,10]
    const float* wp    = (const float*)d_in[2];   // [8,128,128,8]
    // d_in[3] = tensor_masks (all ones, no effect on the reference math)
    const float* W     = (const float*)d_in[4];   // [10,994]
    const float* bias  = (const float*)d_in[5];   // [10]
    float* out = (float*)d_out;                   // [8,128,128,10]

    precompute_rows<<<B_ * S_ / 4, 256>>>(gcn, wp, W, bias);
    combine_kernel<<<B_ * S_ / 2, 128>>>(label, wp, W, out);
}